// round 2
// baseline (speedup 1.0000x reference)
#include <cuda_runtime.h>
#include <math.h>
#include <stdint.h>

#define SS 512
#define BB 64
#define II 1024
#define HH 1024
#define SB (SS*BB)

// ---------------- scratch (static device globals; no allocation) -------------
__device__ float g_XP[4ULL * SB * HH];        // input projections, plane per gate [4][S*B][H]
__device__ float g_Hall[(size_t)SB * HH];     // h_t for every step  [S][B][H]
__device__ float g_C[2][BB * HH];             // cell state ping-pong
__device__ float g_H0[BB * HH];               // zero initial hidden state

// ---------------- init -------------------------------------------------------
__global__ void init_state_kernel() {
    int idx = blockIdx.x * blockDim.x + threadIdx.x;
    if (idx < BB * HH) {
        g_H0[idx]   = 0.0f;
        g_C[0][idx] = 0.0f;
    }
}

// ---------------- SGEMM core: C[M,N] = A[M,K] @ Bw[K,N] + bias[N] ------------
// Row-major everything. Requires M%128==0, N%128==0, K%8==0 (true for all uses).
// 128x128 block tile, BK=8, 256 threads, 8x8 per-thread register tile.
__device__ __forceinline__ void sgemm_core(
    const float* __restrict__ A, const float* __restrict__ Bw,
    const float* __restrict__ bias, float* __restrict__ C,
    int M, int N, int K)
{
    __shared__ __align__(16) float As[8][128];   // transposed: As[k][m]
    __shared__ __align__(16) float Bs[8][128];   // Bs[k][n]

    const int tid  = threadIdx.x;
    const int brow = blockIdx.y;
    const int bcol = blockIdx.x;

    const float* Ab = A + (size_t)brow * 128 * K;
    const float* Bb = Bw + bcol * 128;

    const int arow  = tid >> 1;          // 0..127
    const int acol  = (tid & 1) * 4;     // 0 or 4
    const int brow8 = tid >> 5;          // 0..7
    const int bcol4 = (tid & 31) * 4;    // 0..124
    const int ty    = tid >> 4;          // 0..15
    const int tx    = tid & 15;          // 0..15

    float acc[8][8];
    #pragma unroll
    for (int i = 0; i < 8; ++i)
        #pragma unroll
        for (int j = 0; j < 8; ++j) acc[i][j] = 0.0f;

    for (int k0 = 0; k0 < K; k0 += 8) {
        float4 av = *(const float4*)(Ab + (size_t)arow * K + k0 + acol);
        As[acol + 0][arow] = av.x;
        As[acol + 1][arow] = av.y;
        As[acol + 2][arow] = av.z;
        As[acol + 3][arow] = av.w;
        float4 bv = *(const float4*)(Bb + (size_t)(k0 + brow8) * N + bcol4);
        *(float4*)&Bs[brow8][bcol4] = bv;
        __syncthreads();

        #pragma unroll
        for (int k = 0; k < 8; ++k) {
            float ar[8], br[8];
            *(float4*)&ar[0] = *(const float4*)&As[k][ty * 8];
            *(float4*)&ar[4] = *(const float4*)&As[k][ty * 8 + 4];
            *(float4*)&br[0] = *(const float4*)&Bs[k][tx * 8];
            *(float4*)&br[4] = *(const float4*)&Bs[k][tx * 8 + 4];
            #pragma unroll
            for (int i = 0; i < 8; ++i)
                #pragma unroll
                for (int j = 0; j < 8; ++j)
                    acc[i][j] += ar[i] * br[j];
        }
        __syncthreads();
    }

    #pragma unroll
    for (int i = 0; i < 8; ++i) {
        int r = brow * 128 + ty * 8 + i;
        float*       Crow = C    + (size_t)r * N + bcol * 128 + tx * 8;
        const float* bp   = bias + bcol * 128 + tx * 8;
        #pragma unroll
        for (int j = 0; j < 8; ++j) Crow[j] = acc[i][j] + bp[j];
    }
}

// Input projection: writes into g_XP plane `gate`.
__global__ __launch_bounds__(256) void sgemm_xproj(
    const float* __restrict__ A, const float* __restrict__ Bw,
    const float* __restrict__ bias, int gate, int M, int N, int K)
{
    float* C = g_XP + (size_t)gate * SB * HH;
    sgemm_core(A, Bw, bias, C, M, N, K);
}

// Output GEMM: A = g_Hall (all hidden states), C = d_out.
__global__ __launch_bounds__(256) void sgemm_out(
    const float* __restrict__ Bw, const float* __restrict__ bias,
    float* __restrict__ C, int M, int N, int K)
{
    sgemm_core(g_Hall, Bw, bias, C, M, N, K);
}

// ---------------- Recurrent step --------------------------------------------
// One launch per t. Block b handles 8 hidden columns [b*8, b*8+8) for ALL 64
// batch rows and ALL 4 gates: pre[g][64,8] = h_prev @ W_h[g] (K=1024).
// Then fuses xp + bias + nonlinearities + cell update + h write.
// 128 blocks x 256 threads. Per thread: 2 rows x 1 col x 4 gates.
#define STEP_BK 16
__global__ __launch_bounds__(256) void lstm_step(
    int t,
    const float* __restrict__ Wi, const float* __restrict__ Wf,
    const float* __restrict__ Wc, const float* __restrict__ Wo,
    const float* __restrict__ bi, const float* __restrict__ bf,
    const float* __restrict__ bc, const float* __restrict__ bo)
{
    __shared__ __align__(16) float As[STEP_BK][BB + 2];   // h_prev^T: As[k][row]
    __shared__ __align__(16) float Bs[STEP_BK][8][4];     // Bs[k][col][gate]

    const float* hprev = (t == 0) ? g_H0 : (g_Hall + (size_t)(t - 1) * BB * HH);
    const float* cin   = g_C[t & 1];
    float*       cout  = g_C[(t + 1) & 1];
    float*       hout  = g_Hall + (size_t)t * BB * HH;

    const int tid    = threadIdx.x;
    const int c0     = blockIdx.x * 8;
    const int colIdx = tid & 7;          // 0..7
    const int rp     = tid >> 3;         // 0..31 row pair

    const int lr  = tid >> 2;            // 0..63  A-load row
    const int lc4 = (tid & 3) * 4;       // A-load k offset

    const float* W[4] = {Wi, Wf, Wc, Wo};

    float acc[2][4];
    #pragma unroll
    for (int r = 0; r < 2; ++r)
        #pragma unroll
        for (int g = 0; g < 4; ++g) acc[r][g] = 0.0f;

    for (int k0 = 0; k0 < HH; k0 += STEP_BK) {
        float4 av = *(const float4*)(hprev + (size_t)lr * HH + k0 + lc4);
        As[lc4 + 0][lr] = av.x;
        As[lc4 + 1][lr] = av.y;
        As[lc4 + 2][lr] = av.z;
        As[lc4 + 3][lr] = av.w;

        #pragma unroll
        for (int e = 0; e < 2; ++e) {
            int idx  = tid * 2 + e;          // 0..511
            int gate = idx >> 7;             // 0..3
            int rem  = idx & 127;
            int kk   = rem >> 3;             // 0..15
            int cc   = rem & 7;              // 0..7
            Bs[kk][cc][gate] = W[gate][(size_t)(k0 + kk) * HH + c0 + cc];
        }
        __syncthreads();

        #pragma unroll
        for (int k = 0; k < STEP_BK; ++k) {
            float2 a2 = *(const float2*)&As[k][rp * 2];
            float4 b4 = *(const float4*)&Bs[k][colIdx][0];
            acc[0][0] += a2.x * b4.x;  acc[0][1] += a2.x * b4.y;
            acc[0][2] += a2.x * b4.z;  acc[0][3] += a2.x * b4.w;
            acc[1][0] += a2.y * b4.x;  acc[1][1] += a2.y * b4.y;
            acc[1][2] += a2.y * b4.z;  acc[1][3] += a2.y * b4.w;
        }
        __syncthreads();
    }

    const int col = c0 + colIdx;
    #pragma unroll
    for (int r = 0; r < 2; ++r) {
        int row = rp * 2 + r;
        size_t off   = (size_t)row * HH + col;
        size_t xpoff = (size_t)t * BB * HH + off;

        float pre_i = acc[r][0] + g_XP[0ULL * SB * HH + xpoff] + bi[col];
        float pre_f = acc[r][1] + g_XP[1ULL * SB * HH + xpoff] + bf[col];
        float pre_c = acc[r][2] + g_XP[2ULL * SB * HH + xpoff] + bc[col];
        float pre_o = acc[r][3] + g_XP[3ULL * SB * HH + xpoff] + bo[col];

        float iv = 1.0f / (1.0f + expf(-pre_i));
        float fv = 1.0f / (1.0f + expf(-pre_f));
        float ov = 1.0f / (1.0f + expf(-pre_o));
        float gv = tanhf(pre_c);

        float cv = fv * cin[off] + iv * gv;
        float hv = ov * tanhf(cv);

        cout[off] = cv;
        hout[off] = hv;
    }
}

// ---------------- launch -----------------------------------------------------
extern "C" void kernel_launch(void* const* d_in, const int* in_sizes, int n_in,
                              void* d_out, int out_size)
{
    (void)in_sizes; (void)n_in; (void)out_size;

    const float* x    = (const float*)d_in[0];
    const float* Wx[4] = {(const float*)d_in[1], (const float*)d_in[3],
                          (const float*)d_in[5], (const float*)d_in[7]};
    const float* bx[4] = {(const float*)d_in[2], (const float*)d_in[4],
                          (const float*)d_in[6], (const float*)d_in[8]};
    const float* Wh[4] = {(const float*)d_in[9],  (const float*)d_in[11],
                          (const float*)d_in[13], (const float*)d_in[15]};
    const float* bh[4] = {(const float*)d_in[10], (const float*)d_in[12],
                          (const float*)d_in[14], (const float*)d_in[16]};
    const float* Why = (const float*)d_in[17];
    const float* bhy = (const float*)d_in[18];
    float* out = (float*)d_out;

    // 1) reset h0/c0 (buffers persist across calls; must re-zero每 call)
    init_state_kernel<<<(BB * HH + 255) / 256, 256>>>();

    // 2) input projections: XP[g] = x @ W_x[g] + b_x[g]   (M=32768,N=1024,K=1024)
    {
        dim3 grid(HH / 128, SB / 128);
        for (int g = 0; g < 4; ++g)
            sgemm_xproj<<<grid, 256>>>(x, Wx[g], bx[g], g, SB, HH, II);
    }

    // 3) recurrence: 512 sequential steps
    for (int t = 0; t < SS; ++t) {
        lstm_step<<<HH / 8, 256>>>(t, Wh[0], Wh[1], Wh[2], Wh[3],
                                      bh[0], bh[1], bh[2], bh[3]);
    }

    // 4) output projection: Y = H_all @ W_hy + b_hy  (M=32768,N=1024,K=1024)
    {
        dim3 grid(HH / 128, SB / 128);
        sgemm_out<<<grid, 256>>>(Why, bhy, out, SB, HH, HH);
    }
}

// round 3
// speedup vs baseline: 2.2710x; 2.2710x over previous
#include <cuda_runtime.h>
#include <math.h>
#include <stdint.h>

#define SS 512
#define BB 64
#define II 1024
#define HH 1024
#define SB (SS*BB)

// ---------------- scratch (static device globals; no allocation) -------------
__device__ float g_XP[4ULL * SB * HH];        // input projections [4][S*B][H]
__device__ float g_Hall[(size_t)SB * HH];     // h_t for every step [S][B][H]
__device__ float g_C[2][BB * HH];             // cell state ping-pong
__device__ float g_H0[BB * HH];               // zero initial hidden state

// ---------------- helpers ----------------------------------------------------
__device__ __forceinline__ float f2tf32(float f) {
    uint32_t r;
    asm("cvt.rna.tf32.f32 %0, %1;" : "=r"(r) : "f"(f));
    return __uint_as_float(r);
}

__device__ __forceinline__ void mma_tf32(float c[4], const uint32_t a[4], const uint32_t b[2]) {
    asm volatile(
        "mma.sync.aligned.m16n8k8.row.col.f32.tf32.tf32.f32 "
        "{%0,%1,%2,%3}, {%4,%5,%6,%7}, {%8,%9}, {%0,%1,%2,%3};"
        : "+f"(c[0]), "+f"(c[1]), "+f"(c[2]), "+f"(c[3])
        : "r"(a[0]), "r"(a[1]), "r"(a[2]), "r"(a[3]), "r"(b[0]), "r"(b[1]));
}

// ---------------- init -------------------------------------------------------
__global__ void init_state_kernel() {
    int idx = blockIdx.x * blockDim.x + threadIdx.x;
    if (idx < BB * HH) {
        g_H0[idx]   = 0.0f;
        g_C[0][idx] = 0.0f;
    }
}

// ---------------- big tf32 GEMM: C[M,N]=A[M,K]@B[K,N]+bias, N=K=1024 --------
// Block tile 128x128, K-step 32, 256 threads (8 warps, 2m x 4n), warp 64x32.
// Single smem buffer + register prefetch, 2 syncs/iter.
#define BM 128
#define BN 128
#define BKK 32

__device__ __forceinline__ void gemm_tf32_core(
    const float* __restrict__ A, const float* __restrict__ Bw,
    const float* __restrict__ bias, float* __restrict__ C)
{
    __shared__ __align__(16) float As[BM][BKK + 4];   // [m][k] stride 36
    __shared__ __align__(16) float Bs[BKK][BN + 4];   // [k][n] stride 132

    const int tid  = threadIdx.x;
    const int lane = tid & 31;
    const int w    = tid >> 5;
    const int wm   = w & 1;      // 0..1  (64-row half)
    const int wn   = w >> 1;     // 0..3  (32-col quarter)

    const int m0 = blockIdx.y * BM;
    const int n0 = blockIdx.x * BN;

    // global load indices
    const int amr = tid >> 3;          // 0..31 (+32*i)
    const int akc = (tid & 7) * 4;
    const int bkr = tid >> 5;          // 0..7  (+8*i)
    const int bnc = (tid & 31) * 4;

    float acc[4][4][4];
    #pragma unroll
    for (int i = 0; i < 4; ++i)
        #pragma unroll
        for (int j = 0; j < 4; ++j)
            #pragma unroll
            for (int r = 0; r < 4; ++r) acc[i][j][r] = 0.0f;

    float4 pa[4], pb[4];
    // preload tile 0
    #pragma unroll
    for (int i = 0; i < 4; ++i) {
        pa[i] = *(const float4*)(A  + (size_t)(m0 + amr + 32 * i) * II + akc);
        pb[i] = *(const float4*)(Bw + (size_t)(bkr + 8 * i) * HH + n0 + bnc);
    }
    #pragma unroll
    for (int i = 0; i < 4; ++i) {
        As[amr + 32 * i][akc + 0] = f2tf32(pa[i].x);
        As[amr + 32 * i][akc + 1] = f2tf32(pa[i].y);
        As[amr + 32 * i][akc + 2] = f2tf32(pa[i].z);
        As[amr + 32 * i][akc + 3] = f2tf32(pa[i].w);
        float4 t = pb[i];
        t.x = f2tf32(t.x); t.y = f2tf32(t.y); t.z = f2tf32(t.z); t.w = f2tf32(t.w);
        *(float4*)&Bs[bkr + 8 * i][bnc] = t;
    }
    __syncthreads();

    const int NT = II / BKK;   // 32
    for (int it = 0; it < NT; ++it) {
        const int knext = (it + 1) * BKK;
        if (knext < II) {
            #pragma unroll
            for (int i = 0; i < 4; ++i) {
                pa[i] = *(const float4*)(A  + (size_t)(m0 + amr + 32 * i) * II + knext + akc);
                pb[i] = *(const float4*)(Bw + (size_t)(knext + bkr + 8 * i) * HH + n0 + bnc);
            }
        }

        #pragma unroll
        for (int kk = 0; kk < 4; ++kk) {
            const int kb = kk * 8;
            uint32_t af[4][4], bf[4][2];
            #pragma unroll
            for (int mt = 0; mt < 4; ++mt) {
                int r = wm * 64 + mt * 16 + (lane >> 2);
                int c = kb + (lane & 3);
                af[mt][0] = __float_as_uint(As[r][c]);
                af[mt][1] = __float_as_uint(As[r + 8][c]);
                af[mt][2] = __float_as_uint(As[r][c + 4]);
                af[mt][3] = __float_as_uint(As[r + 8][c + 4]);
            }
            #pragma unroll
            for (int nt = 0; nt < 4; ++nt) {
                int n = wn * 32 + nt * 8 + (lane >> 2);
                bf[nt][0] = __float_as_uint(Bs[kb + (lane & 3)][n]);
                bf[nt][1] = __float_as_uint(Bs[kb + 4 + (lane & 3)][n]);
            }
            #pragma unroll
            for (int mt = 0; mt < 4; ++mt)
                #pragma unroll
                for (int nt = 0; nt < 4; ++nt)
                    mma_tf32(acc[mt][nt], af[mt], bf[nt]);
        }

        if (knext < II) {
            __syncthreads();
            #pragma unroll
            for (int i = 0; i < 4; ++i) {
                As[amr + 32 * i][akc + 0] = f2tf32(pa[i].x);
                As[amr + 32 * i][akc + 1] = f2tf32(pa[i].y);
                As[amr + 32 * i][akc + 2] = f2tf32(pa[i].z);
                As[amr + 32 * i][akc + 3] = f2tf32(pa[i].w);
                float4 t = pb[i];
                t.x = f2tf32(t.x); t.y = f2tf32(t.y); t.z = f2tf32(t.z); t.w = f2tf32(t.w);
                *(float4*)&Bs[bkr + 8 * i][bnc] = t;
            }
            __syncthreads();
        }
    }

    // epilogue
    #pragma unroll
    for (int mt = 0; mt < 4; ++mt) {
        int row = m0 + wm * 64 + mt * 16 + (lane >> 2);
        #pragma unroll
        for (int nt = 0; nt < 4; ++nt) {
            int col = n0 + wn * 32 + nt * 8 + 2 * (lane & 3);
            float b0 = bias[col], b1 = bias[col + 1];
            float2 v0 = {acc[mt][nt][0] + b0, acc[mt][nt][1] + b1};
            float2 v1 = {acc[mt][nt][2] + b0, acc[mt][nt][3] + b1};
            *(float2*)&C[(size_t)row * HH + col]       = v0;
            *(float2*)&C[(size_t)(row + 8) * HH + col] = v1;
        }
    }
}

__global__ __launch_bounds__(256) void gemm_xproj(
    const float* __restrict__ x,
    const float* __restrict__ W0, const float* __restrict__ W1,
    const float* __restrict__ W2, const float* __restrict__ W3,
    const float* __restrict__ b0, const float* __restrict__ b1,
    const float* __restrict__ b2, const float* __restrict__ b3)
{
    const float* Ws[4] = {W0, W1, W2, W3};
    const float* bs[4] = {b0, b1, b2, b3};
    int g = blockIdx.z;
    gemm_tf32_core(x, Ws[g], bs[g], g_XP + (size_t)g * SB * HH);
}

__global__ __launch_bounds__(256) void gemm_outproj(
    const float* __restrict__ Why, const float* __restrict__ bhy,
    float* __restrict__ out)
{
    gemm_tf32_core(g_Hall, Why, bhy, out);
}

// ---------------- Recurrent step (tensor-core) -------------------------------
// Grid 64 blocks x 256 threads. Block handles 16 H-columns x all 4 gates x all
// 64 batch rows: pre[64][64], col = gate*16 + cc. K=1024, K-step 32.
// Warps: 8 = 4(m-tiles of 16 rows) x 2(n halves of 32 cols).
__global__ __launch_bounds__(256) void lstm_step(
    int t,
    const float* __restrict__ Wi, const float* __restrict__ Wf,
    const float* __restrict__ Wc, const float* __restrict__ Wo,
    const float* __restrict__ bi, const float* __restrict__ bf,
    const float* __restrict__ bc, const float* __restrict__ bo)
{
    __shared__ __align__(16) float As[BB][36];       // h_prev tile [row][k]
    __shared__ __align__(16) float Bs[32][68];       // weights [k][g*16+cc]
    __shared__ __align__(16) float pre[BB][68];      // pre-activations

    const float* hprev = (t == 0) ? g_H0 : (g_Hall + (size_t)(t - 1) * BB * HH);
    const float* cin   = g_C[t & 1];
    float*       cout  = g_C[(t + 1) & 1];
    float*       hout  = g_Hall + (size_t)t * BB * HH;
    const float* W[4]  = {Wi, Wf, Wc, Wo};
    const float* bvec[4] = {bi, bf, bc, bo};

    const int tid  = threadIdx.x;
    const int lane = tid & 31;
    const int w    = tid >> 5;
    const int wm   = w & 3;      // m-tile (16 rows)
    const int wn   = w >> 2;     // n half (32 cols)
    const int c0   = blockIdx.x * 16;

    // loads: A 64x32 (2 float4/thr), B 4x(32x16) (2 float4/thr)
    const int amr = tid >> 3;          // 0..31 (+32)
    const int akc = (tid & 7) * 4;

    float acc[4][4];
    #pragma unroll
    for (int nt = 0; nt < 4; ++nt)
        #pragma unroll
        for (int r = 0; r < 4; ++r) acc[nt][r] = 0.0f;

    float4 pa[2], pb[2];
    int bg[2], br[2], bc4[2];
    #pragma unroll
    for (int i = 0; i < 2; ++i) {
        int idx = tid + 256 * i;        // 0..511
        bg[i]  = idx >> 7;              // gate
        br[i]  = (idx >> 2) & 31;       // k row
        bc4[i] = (idx & 3) * 4;         // col offset
    }

    // preload tile 0
    #pragma unroll
    for (int i = 0; i < 2; ++i) {
        pa[i] = *(const float4*)(hprev + (size_t)(amr + 32 * i) * HH + akc);
        pb[i] = *(const float4*)(W[bg[i]] + (size_t)br[i] * HH + c0 + bc4[i]);
    }
    #pragma unroll
    for (int i = 0; i < 2; ++i) {
        As[amr + 32 * i][akc + 0] = f2tf32(pa[i].x);
        As[amr + 32 * i][akc + 1] = f2tf32(pa[i].y);
        As[amr + 32 * i][akc + 2] = f2tf32(pa[i].z);
        As[amr + 32 * i][akc + 3] = f2tf32(pa[i].w);
        float4 v = pb[i];
        v.x = f2tf32(v.x); v.y = f2tf32(v.y); v.z = f2tf32(v.z); v.w = f2tf32(v.w);
        *(float4*)&Bs[br[i]][bg[i] * 16 + bc4[i]] = v;
    }
    __syncthreads();

    for (int it = 0; it < HH / 32; ++it) {
        const int knext = (it + 1) * 32;
        if (knext < HH) {
            #pragma unroll
            for (int i = 0; i < 2; ++i) {
                pa[i] = *(const float4*)(hprev + (size_t)(amr + 32 * i) * HH + knext + akc);
                pb[i] = *(const float4*)(W[bg[i]] + (size_t)(knext + br[i]) * HH + c0 + bc4[i]);
            }
        }

        #pragma unroll
        for (int kk = 0; kk < 4; ++kk) {
            const int kb = kk * 8;
            uint32_t af[4], bf[4][2];
            {
                int r = wm * 16 + (lane >> 2);
                int c = kb + (lane & 3);
                af[0] = __float_as_uint(As[r][c]);
                af[1] = __float_as_uint(As[r + 8][c]);
                af[2] = __float_as_uint(As[r][c + 4]);
                af[3] = __float_as_uint(As[r + 8][c + 4]);
            }
            #pragma unroll
            for (int nt = 0; nt < 4; ++nt) {
                int n = wn * 32 + nt * 8 + (lane >> 2);
                bf[nt][0] = __float_as_uint(Bs[kb + (lane & 3)][n]);
                bf[nt][1] = __float_as_uint(Bs[kb + 4 + (lane & 3)][n]);
            }
            #pragma unroll
            for (int nt = 0; nt < 4; ++nt)
                mma_tf32(acc[nt], af, bf[nt]);
        }

        if (knext < HH) {
            __syncthreads();
            #pragma unroll
            for (int i = 0; i < 2; ++i) {
                As[amr + 32 * i][akc + 0] = f2tf32(pa[i].x);
                As[amr + 32 * i][akc + 1] = f2tf32(pa[i].y);
                As[amr + 32 * i][akc + 2] = f2tf32(pa[i].z);
                As[amr + 32 * i][akc + 3] = f2tf32(pa[i].w);
                float4 v = pb[i];
                v.x = f2tf32(v.x); v.y = f2tf32(v.y); v.z = f2tf32(v.z); v.w = f2tf32(v.w);
                *(float4*)&Bs[br[i]][bg[i] * 16 + bc4[i]] = v;
            }
            __syncthreads();
        }
    }

    // stage pre-activations through smem
    #pragma unroll
    for (int nt = 0; nt < 4; ++nt) {
        int row = wm * 16 + (lane >> 2);
        int col = wn * 32 + nt * 8 + 2 * (lane & 3);
        pre[row][col]         = acc[nt][0];
        pre[row][col + 1]     = acc[nt][1];
        pre[row + 8][col]     = acc[nt][2];
        pre[row + 8][col + 1] = acc[nt][3];
    }
    __syncthreads();

    // fused elementwise epilogue: 64 rows x 16 cols, 4 per thread
    #pragma unroll
    for (int i = 0; i < 4; ++i) {
        int p   = tid + 256 * i;
        int row = p >> 4;
        int cc  = p & 15;
        int col = c0 + cc;
        size_t off   = (size_t)row * HH + col;
        size_t xpoff = (size_t)t * BB * HH + off;

        float pi = pre[row][cc]      + g_XP[0ULL * SB * HH + xpoff] + bvec[0][col];
        float pf = pre[row][16 + cc] + g_XP[1ULL * SB * HH + xpoff] + bvec[1][col];
        float pc = pre[row][32 + cc] + g_XP[2ULL * SB * HH + xpoff] + bvec[2][col];
        float po = pre[row][48 + cc] + g_XP[3ULL * SB * HH + xpoff] + bvec[3][col];

        float iv = 1.0f / (1.0f + expf(-pi));
        float fv = 1.0f / (1.0f + expf(-pf));
        float ov = 1.0f / (1.0f + expf(-po));
        float gv = tanhf(pc);

        float cv = fv * cin[off] + iv * gv;
        float hv = ov * tanhf(cv);

        cout[off] = cv;
        hout[off] = hv;
    }
}

// ---------------- launch -----------------------------------------------------
extern "C" void kernel_launch(void* const* d_in, const int* in_sizes, int n_in,
                              void* d_out, int out_size)
{
    (void)in_sizes; (void)n_in; (void)out_size;

    const float* x    = (const float*)d_in[0];
    const float* Wx[4] = {(const float*)d_in[1], (const float*)d_in[3],
                          (const float*)d_in[5], (const float*)d_in[7]};
    const float* bx[4] = {(const float*)d_in[2], (const float*)d_in[4],
                          (const float*)d_in[6], (const float*)d_in[8]};
    const float* Wh[4] = {(const float*)d_in[9],  (const float*)d_in[11],
                          (const float*)d_in[13], (const float*)d_in[15]};
    const float* bh[4] = {(const float*)d_in[10], (const float*)d_in[12],
                          (const float*)d_in[14], (const float*)d_in[16]};
    const float* Why = (const float*)d_in[17];
    const float* bhy = (const float*)d_in[18];
    float* out = (float*)d_out;

    init_state_kernel<<<(BB * HH + 255) / 256, 256>>>();

    // input projections: XP[g] = x @ W_x[g] + b_x[g]
    {
        dim3 grid(HH / BN, SB / BM, 4);
        gemm_xproj<<<grid, 256>>>(x, Wx[0], Wx[1], Wx[2], Wx[3],
                                     bx[0], bx[1], bx[2], bx[3]);
    }

    // recurrence: 512 sequential steps
    for (int t = 0; t < SS; ++t) {
        lstm_step<<<64, 256>>>(t, Wh[0], Wh[1], Wh[2], Wh[3],
                                  bh[0], bh[1], bh[2], bh[3]);
    }

    // output projection: Y = H_all @ W_hy + b_hy
    {
        dim3 grid(HH / BN, SB / BM);
        gemm_outproj<<<grid, 256>>>(Why, bhy, out);
    }
}

// round 4
// speedup vs baseline: 3.9998x; 1.7613x over previous
#include <cuda_runtime.h>
#include <math.h>
#include <stdint.h>

#define SS 512
#define BB 64
#define II 1024
#define HH 1024
#define SB (SS*BB)

// ---------------- scratch (static device globals; no allocation) -------------
__device__ float g_XP[4ULL * SB * HH];          // input projections [4][S*B][H]
__device__ float g_Hall[(size_t)SB * HH];       // h_t row-major [S][B][H] (for out GEMM)
__device__ float g_C[2][BB * HH];               // cell state ping-pong
__device__ float g_HTp[2][HH * BB];             // h transposed+pair-packed, ping-pong
__device__ float g_Wpk[128ULL * 128 * 32 * 8];  // packed recurrent weights [bx][k8][pcol][p][hi]

// ---------------- helpers ----------------------------------------------------
__device__ __forceinline__ float f2tf32(float f) {
    uint32_t r;
    asm("cvt.rna.tf32.f32 %0, %1;" : "=r"(r) : "f"(f));
    return __uint_as_float(r);
}

__device__ __forceinline__ void mma_tf32(float c[4], const uint32_t a[4], const uint32_t b[2]) {
    asm volatile(
        "mma.sync.aligned.m16n8k8.row.col.f32.tf32.tf32.f32 "
        "{%0,%1,%2,%3}, {%4,%5,%6,%7}, {%8,%9}, {%0,%1,%2,%3};"
        : "+f"(c[0]), "+f"(c[1]), "+f"(c[2]), "+f"(c[3])
        : "r"(a[0]), "r"(a[1]), "r"(a[2]), "r"(a[3]), "r"(b[0]), "r"(b[1]));
}

__device__ __forceinline__ void cp_async16(uint32_t dst_smem, const void* src) {
    asm volatile("cp.async.cg.shared.global [%0], [%1], 16;" :: "r"(dst_smem), "l"(src));
}
__device__ __forceinline__ void cp_commit() { asm volatile("cp.async.commit_group;"); }
template<int N> __device__ __forceinline__ void cp_wait() {
    asm volatile("cp.async.wait_group %0;" :: "n"(N));
}

// ---------------- init -------------------------------------------------------
__global__ void init_state_kernel() {
    int idx = blockIdx.x * blockDim.x + threadIdx.x;
    if (idx < BB * HH) {
        g_C[0][idx]   = 0.0f;
        g_HTp[0][idx] = 0.0f;
    }
}

// ---------------- weight repack ----------------------------------------------
// g_Wpk[((bx*128 + k8)*32 + pcol)*8 + p*2 + hi] = tf32(W[gate][k][bx*8+cc])
//   gate = pcol>>3, cc = pcol&7, k = k8*8 + p + hi*4
__global__ __launch_bounds__(256) void repack_w(
    const float* __restrict__ Wi, const float* __restrict__ Wf,
    const float* __restrict__ Wc, const float* __restrict__ Wo)
{
    const float* W[4] = {Wi, Wf, Wc, Wo};
    int n = blockIdx.x * blockDim.x + threadIdx.x;   // 0 .. 4194303
    int hi   = n & 1;
    int p    = (n >> 1) & 3;
    int pcol = (n >> 3) & 31;
    int k8   = (n >> 8) & 127;
    int bx   = n >> 15;
    int gate = pcol >> 3;
    int col  = bx * 8 + (pcol & 7);
    int k    = k8 * 8 + p + hi * 4;
    g_Wpk[n] = f2tf32(W[gate][(size_t)k * HH + col]);
}

// ---------------- big tf32 GEMM (unchanged from R3) --------------------------
#define BM 128
#define BN 128
#define BKK 32

__device__ __forceinline__ void gemm_tf32_core(
    const float* __restrict__ A, const float* __restrict__ Bw,
    const float* __restrict__ bias, float* __restrict__ C)
{
    __shared__ __align__(16) float As[BM][BKK + 4];
    __shared__ __align__(16) float Bs[BKK][BN + 4];

    const int tid  = threadIdx.x;
    const int lane = tid & 31;
    const int w    = tid >> 5;
    const int wm   = w & 1;
    const int wn   = w >> 1;

    const int m0 = blockIdx.y * BM;
    const int n0 = blockIdx.x * BN;

    const int amr = tid >> 3;
    const int akc = (tid & 7) * 4;
    const int bkr = tid >> 5;
    const int bnc = (tid & 31) * 4;

    float acc[4][4][4];
    #pragma unroll
    for (int i = 0; i < 4; ++i)
        #pragma unroll
        for (int j = 0; j < 4; ++j)
            #pragma unroll
            for (int r = 0; r < 4; ++r) acc[i][j][r] = 0.0f;

    float4 pa[4], pb[4];
    #pragma unroll
    for (int i = 0; i < 4; ++i) {
        pa[i] = *(const float4*)(A  + (size_t)(m0 + amr + 32 * i) * II + akc);
        pb[i] = *(const float4*)(Bw + (size_t)(bkr + 8 * i) * HH + n0 + bnc);
    }
    #pragma unroll
    for (int i = 0; i < 4; ++i) {
        As[amr + 32 * i][akc + 0] = f2tf32(pa[i].x);
        As[amr + 32 * i][akc + 1] = f2tf32(pa[i].y);
        As[amr + 32 * i][akc + 2] = f2tf32(pa[i].z);
        As[amr + 32 * i][akc + 3] = f2tf32(pa[i].w);
        float4 t = pb[i];
        t.x = f2tf32(t.x); t.y = f2tf32(t.y); t.z = f2tf32(t.z); t.w = f2tf32(t.w);
        *(float4*)&Bs[bkr + 8 * i][bnc] = t;
    }
    __syncthreads();

    const int NT = II / BKK;
    for (int it = 0; it < NT; ++it) {
        const int knext = (it + 1) * BKK;
        if (knext < II) {
            #pragma unroll
            for (int i = 0; i < 4; ++i) {
                pa[i] = *(const float4*)(A  + (size_t)(m0 + amr + 32 * i) * II + knext + akc);
                pb[i] = *(const float4*)(Bw + (size_t)(knext + bkr + 8 * i) * HH + n0 + bnc);
            }
        }
        #pragma unroll
        for (int kk = 0; kk < 4; ++kk) {
            const int kb = kk * 8;
            uint32_t af[4][4], bf[4][2];
            #pragma unroll
            for (int mt = 0; mt < 4; ++mt) {
                int r = wm * 64 + mt * 16 + (lane >> 2);
                int c = kb + (lane & 3);
                af[mt][0] = __float_as_uint(As[r][c]);
                af[mt][1] = __float_as_uint(As[r + 8][c]);
                af[mt][2] = __float_as_uint(As[r][c + 4]);
                af[mt][3] = __float_as_uint(As[r + 8][c + 4]);
            }
            #pragma unroll
            for (int nt = 0; nt < 4; ++nt) {
                int n = wn * 32 + nt * 8 + (lane >> 2);
                bf[nt][0] = __float_as_uint(Bs[kb + (lane & 3)][n]);
                bf[nt][1] = __float_as_uint(Bs[kb + 4 + (lane & 3)][n]);
            }
            #pragma unroll
            for (int mt = 0; mt < 4; ++mt)
                #pragma unroll
                for (int nt = 0; nt < 4; ++nt)
                    mma_tf32(acc[mt][nt], af[mt], bf[nt]);
        }
        if (knext < II) {
            __syncthreads();
            #pragma unroll
            for (int i = 0; i < 4; ++i) {
                As[amr + 32 * i][akc + 0] = f2tf32(pa[i].x);
                As[amr + 32 * i][akc + 1] = f2tf32(pa[i].y);
                As[amr + 32 * i][akc + 2] = f2tf32(pa[i].z);
                As[amr + 32 * i][akc + 3] = f2tf32(pa[i].w);
                float4 t = pb[i];
                t.x = f2tf32(t.x); t.y = f2tf32(t.y); t.z = f2tf32(t.z); t.w = f2tf32(t.w);
                *(float4*)&Bs[bkr + 8 * i][bnc] = t;
            }
            __syncthreads();
        }
    }

    #pragma unroll
    for (int mt = 0; mt < 4; ++mt) {
        int row = m0 + wm * 64 + mt * 16 + (lane >> 2);
        #pragma unroll
        for (int nt = 0; nt < 4; ++nt) {
            int col = n0 + wn * 32 + nt * 8 + 2 * (lane & 3);
            float b0 = bias[col], b1 = bias[col + 1];
            float2 v0 = {acc[mt][nt][0] + b0, acc[mt][nt][1] + b1};
            float2 v1 = {acc[mt][nt][2] + b0, acc[mt][nt][3] + b1};
            *(float2*)&C[(size_t)row * HH + col]       = v0;
            *(float2*)&C[(size_t)(row + 8) * HH + col] = v1;
        }
    }
}

__global__ __launch_bounds__(256) void gemm_xproj(
    const float* __restrict__ x,
    const float* __restrict__ W0, const float* __restrict__ W1,
    const float* __restrict__ W2, const float* __restrict__ W3,
    const float* __restrict__ b0, const float* __restrict__ b1,
    const float* __restrict__ b2, const float* __restrict__ b3)
{
    const float* Ws[4] = {W0, W1, W2, W3};
    const float* bs[4] = {b0, b1, b2, b3};
    int g = blockIdx.z;
    gemm_tf32_core(x, Ws[g], bs[g], g_XP + (size_t)g * SB * HH);
}

__global__ __launch_bounds__(256) void gemm_outproj(
    const float* __restrict__ Why, const float* __restrict__ bhy,
    float* __restrict__ out)
{
    gemm_tf32_core(g_Hall, Why, bhy, out);
}

// ---------------- Recurrent step: cp.async pipelined tensor-core -------------
// 128 blocks x 256 threads. Block bx: hidden cols [bx*8, bx*8+8), all 4 gates
// (32 pre-cols), all 64 batch rows. K=1024, BK=32, 3-stage cp.async pipeline.
// 8 warps = 4 m-tiles(16 rows) x 2 n-halves(16 pcols). Fragment-packed smem:
//   A stage: [4 k8][64 row][8]  (pairs k,k+4 adjacent)   8KB
//   B stage: [4 k8][32 pcol][8] (pairs k,k+4 adjacent)   4KB
#define STAGES 3
#define NIT 32

__global__ __launch_bounds__(256) void lstm_step(
    int t,
    const float* __restrict__ bi, const float* __restrict__ bf,
    const float* __restrict__ bc, const float* __restrict__ bo)
{
    __shared__ __align__(16) float As_sm[STAGES * 2048];
    __shared__ __align__(16) float Bs_sm[STAGES * 1024];
    __shared__ __align__(16) float pre[BB][33];

    const int tid  = threadIdx.x;
    const int lane = tid & 31;
    const int w    = tid >> 5;
    const int wm   = w & 3;        // m-tile (16 rows)
    const int wn   = w >> 2;       // n-half (16 pcols)
    const int bx   = blockIdx.x;

    const float* Asrc = g_HTp[t & 1];                       // 2048 floats per stage
    const float* Bsrc = g_Wpk + (size_t)bx * 128 * 256;     // 1024 floats per stage
    const float* cin  = g_C[t & 1];
    float*       cout = g_C[(t + 1) & 1];
    float*       hout = g_Hall + (size_t)t * BB * HH;
    float*       hTn  = g_HTp[(t + 1) & 1];

    const uint32_t sA = (uint32_t)__cvta_generic_to_shared(As_sm);
    const uint32_t sB = (uint32_t)__cvta_generic_to_shared(Bs_sm);

    float acc[2][4];
    #pragma unroll
    for (int nt = 0; nt < 2; ++nt)
        #pragma unroll
        for (int r = 0; r < 4; ++r) acc[nt][r] = 0.0f;

    // ---- issue stage i into slot ----
    auto issue = [&](int i, int slot) {
        // A: 2048 floats = 512 x 16B, 2 per thread
        #pragma unroll
        for (int j = 0; j < 2; ++j) {
            int idx = tid + 256 * j;
            cp_async16(sA + (slot * 2048 + idx * 4) * 4, Asrc + i * 2048 + idx * 4);
        }
        // B: 1024 floats = 256 x 16B, 1 per thread
        cp_async16(sB + (slot * 1024 + tid * 4) * 4, Bsrc + i * 1024 + tid * 4);
    };

    issue(0, 0); cp_commit();
    issue(1, 1); cp_commit();

    for (int it = 0; it < NIT; ++it) {
        cp_wait<1>();
        __syncthreads();
        if (it + 2 < NIT) issue(it + 2, (it + 2) % STAGES);
        cp_commit();

        const int slot = it % STAGES;
        const float* Asl = As_sm + slot * 2048;
        const float* Bsl = Bs_sm + slot * 1024;

        #pragma unroll
        for (int k8 = 0; k8 < 4; ++k8) {
            uint32_t af[4];
            {
                int base = k8 * 512 + (wm * 16 + (lane >> 2)) * 8 + (lane & 3) * 2;
                float2 a0 = *(const float2*)(Asl + base);        // (k, k+4) row r
                float2 a1 = *(const float2*)(Asl + base + 64);   // (k, k+4) row r+8
                af[0] = __float_as_uint(a0.x);
                af[1] = __float_as_uint(a1.x);
                af[2] = __float_as_uint(a0.y);
                af[3] = __float_as_uint(a1.y);
            }
            #pragma unroll
            for (int nt = 0; nt < 2; ++nt) {
                int pb = k8 * 256 + (wn * 16 + nt * 8 + (lane >> 2)) * 8 + (lane & 3) * 2;
                float2 b = *(const float2*)(Bsl + pb);
                uint32_t bfr[2] = {__float_as_uint(b.x), __float_as_uint(b.y)};
                mma_tf32(acc[nt], af, bfr);
            }
        }
    }

    // ---- stage pre-activations through smem ----
    #pragma unroll
    for (int nt = 0; nt < 2; ++nt) {
        int r = wm * 16 + (lane >> 2);
        int c = wn * 16 + nt * 8 + 2 * (lane & 3);
        pre[r][c]         = acc[nt][0];
        pre[r][c + 1]     = acc[nt][1];
        pre[r + 8][c]     = acc[nt][2];
        pre[r + 8][c + 1] = acc[nt][3];
    }
    __syncthreads();

    // ---- fused elementwise epilogue: 64 rows x 8 cols, 2 per thread ----
    const int c0 = bx * 8;
    #pragma unroll
    for (int e = 0; e < 2; ++e) {
        int p   = tid + 256 * e;      // 0..511
        int row = p >> 3;
        int cc  = p & 7;
        int col = c0 + cc;
        size_t off   = (size_t)row * HH + col;
        size_t xpoff = (size_t)t * BB * HH + off;

        float pi = pre[row][cc]      + g_XP[0ULL * SB * HH + xpoff] + bi[col];
        float pf = pre[row][8 + cc]  + g_XP[1ULL * SB * HH + xpoff] + bf[col];
        float pc = pre[row][16 + cc] + g_XP[2ULL * SB * HH + xpoff] + bc[col];
        float po = pre[row][24 + cc] + g_XP[3ULL * SB * HH + xpoff] + bo[col];

        float iv = 1.0f / (1.0f + expf(-pi));
        float fv = 1.0f / (1.0f + expf(-pf));
        float ov = 1.0f / (1.0f + expf(-po));
        float gv = tanhf(pc);

        float cv = fv * cin[off] + iv * gv;
        float hv = ov * tanhf(cv);

        cout[off] = cv;
        hout[off] = hv;
        // transposed + pair-packed for next step's A fragments
        // hTp[((col>>3)*64 + row)*8 + (col&3)*2 + ((col>>2)&1)]
        hTn[(((col >> 3) * 64 + row) << 3) + ((col & 3) << 1) + ((col >> 2) & 1)] = f2tf32(hv);
    }
}

// ---------------- launch -----------------------------------------------------
extern "C" void kernel_launch(void* const* d_in, const int* in_sizes, int n_in,
                              void* d_out, int out_size)
{
    (void)in_sizes; (void)n_in; (void)out_size;

    const float* x    = (const float*)d_in[0];
    const float* Wx[4] = {(const float*)d_in[1], (const float*)d_in[3],
                          (const float*)d_in[5], (const float*)d_in[7]};
    const float* bx[4] = {(const float*)d_in[2], (const float*)d_in[4],
                          (const float*)d_in[6], (const float*)d_in[8]};
    const float* Wh[4] = {(const float*)d_in[9],  (const float*)d_in[11],
                          (const float*)d_in[13], (const float*)d_in[15]};
    const float* bh[4] = {(const float*)d_in[10], (const float*)d_in[12],
                          (const float*)d_in[14], (const float*)d_in[16]};
    const float* Why = (const float*)d_in[17];
    const float* bhy = (const float*)d_in[18];
    float* out = (float*)d_out;

    init_state_kernel<<<(BB * HH + 255) / 256, 256>>>();
    repack_w<<<(128 * 128 * 32 * 8) / 256, 256>>>(Wh[0], Wh[1], Wh[2], Wh[3]);

    // input projections: XP[g] = x @ W_x[g] + b_x[g]
    {
        dim3 grid(HH / BN, SB / BM, 4);
        gemm_xproj<<<grid, 256>>>(x, Wx[0], Wx[1], Wx[2], Wx[3],
                                     bx[0], bx[1], bx[2], bx[3]);
    }

    // recurrence: 512 sequential steps
    for (int t = 0; t < SS; ++t) {
        lstm_step<<<128, 256>>>(t, bh[0], bh[1], bh[2], bh[3]);
    }

    // output projection: Y = H_all @ W_hy + b_hy
    {
        dim3 grid(HH / BN, SB / BM);
        gemm_outproj<<<grid, 256>>>(Why, bhy, out);
    }
}

// round 5
// speedup vs baseline: 4.1253x; 1.0314x over previous
#include <cuda_runtime.h>
#include <math.h>
#include <stdint.h>

#define SS 512
#define BB 64
#define II 1024
#define HH 1024
#define SB (SS*BB)

// ---------------- scratch (static device globals; no allocation) -------------
__device__ float g_XP[4ULL * SB * HH];          // input projections [4][S*B][H]
__device__ float g_Hall[(size_t)SB * HH];       // h_t row-major [S][B][H]
__device__ float g_HTp[2][HH * BB];             // h transposed+pair-packed, ping-pong
__device__ float g_Wpk[128ULL * 128 * 32 * 8];  // packed recurrent weights
__device__ unsigned g_bar;                       // grid barrier (monotonic)

// ---------------- helpers ----------------------------------------------------
__device__ __forceinline__ float f2tf32(float f) {
    uint32_t r;
    asm("cvt.rna.tf32.f32 %0, %1;" : "=r"(r) : "f"(f));
    return __uint_as_float(r);
}

__device__ __forceinline__ void mma_tf32(float c[4], const uint32_t a[4], const uint32_t b[2]) {
    asm volatile(
        "mma.sync.aligned.m16n8k8.row.col.f32.tf32.tf32.f32 "
        "{%0,%1,%2,%3}, {%4,%5,%6,%7}, {%8,%9}, {%0,%1,%2,%3};"
        : "+f"(c[0]), "+f"(c[1]), "+f"(c[2]), "+f"(c[3])
        : "r"(a[0]), "r"(a[1]), "r"(a[2]), "r"(a[3]), "r"(b[0]), "r"(b[1]));
}

__device__ __forceinline__ void cp_async16(uint32_t dst_smem, const void* src) {
    asm volatile("cp.async.cg.shared.global [%0], [%1], 16;" :: "r"(dst_smem), "l"(src));
}
__device__ __forceinline__ void cp_commit() { asm volatile("cp.async.commit_group;"); }
template<int N> __device__ __forceinline__ void cp_wait() {
    asm volatile("cp.async.wait_group %0;" :: "n"(N));
}

// ---------------- init -------------------------------------------------------
__global__ void init_state_kernel() {
    int idx = blockIdx.x * blockDim.x + threadIdx.x;
    if (idx < BB * HH) g_HTp[0][idx] = 0.0f;
    if (idx == 0) g_bar = 0u;
}

// ---------------- weight repack ----------------------------------------------
__global__ __launch_bounds__(256) void repack_w(
    const float* __restrict__ Wi, const float* __restrict__ Wf,
    const float* __restrict__ Wc, const float* __restrict__ Wo)
{
    const float* W[4] = {Wi, Wf, Wc, Wo};
    int n = blockIdx.x * blockDim.x + threadIdx.x;
    int hi   = n & 1;
    int p    = (n >> 1) & 3;
    int pcol = (n >> 3) & 31;
    int k8   = (n >> 8) & 127;
    int bx   = n >> 15;
    int gate = pcol >> 3;
    int col  = bx * 8 + (pcol & 7);
    int k    = k8 * 8 + p + hi * 4;
    g_Wpk[n] = f2tf32(W[gate][(size_t)k * HH + col]);
}

// ---------------- big tf32 GEMM (unchanged) ----------------------------------
#define BM 128
#define BN 128
#define BKK 32

__device__ __forceinline__ void gemm_tf32_core(
    const float* __restrict__ A, const float* __restrict__ Bw,
    const float* __restrict__ bias, float* __restrict__ C)
{
    __shared__ __align__(16) float As[BM][BKK + 4];
    __shared__ __align__(16) float Bs[BKK][BN + 4];

    const int tid  = threadIdx.x;
    const int lane = tid & 31;
    const int w    = tid >> 5;
    const int wm   = w & 1;
    const int wn   = w >> 1;

    const int m0 = blockIdx.y * BM;
    const int n0 = blockIdx.x * BN;

    const int amr = tid >> 3;
    const int akc = (tid & 7) * 4;
    const int bkr = tid >> 5;
    const int bnc = (tid & 31) * 4;

    float acc[4][4][4];
    #pragma unroll
    for (int i = 0; i < 4; ++i)
        #pragma unroll
        for (int j = 0; j < 4; ++j)
            #pragma unroll
            for (int r = 0; r < 4; ++r) acc[i][j][r] = 0.0f;

    float4 pa[4], pb[4];
    #pragma unroll
    for (int i = 0; i < 4; ++i) {
        pa[i] = *(const float4*)(A  + (size_t)(m0 + amr + 32 * i) * II + akc);
        pb[i] = *(const float4*)(Bw + (size_t)(bkr + 8 * i) * HH + n0 + bnc);
    }
    #pragma unroll
    for (int i = 0; i < 4; ++i) {
        As[amr + 32 * i][akc + 0] = f2tf32(pa[i].x);
        As[amr + 32 * i][akc + 1] = f2tf32(pa[i].y);
        As[amr + 32 * i][akc + 2] = f2tf32(pa[i].z);
        As[amr + 32 * i][akc + 3] = f2tf32(pa[i].w);
        float4 t = pb[i];
        t.x = f2tf32(t.x); t.y = f2tf32(t.y); t.z = f2tf32(t.z); t.w = f2tf32(t.w);
        *(float4*)&Bs[bkr + 8 * i][bnc] = t;
    }
    __syncthreads();

    const int NT = II / BKK;
    for (int it = 0; it < NT; ++it) {
        const int knext = (it + 1) * BKK;
        if (knext < II) {
            #pragma unroll
            for (int i = 0; i < 4; ++i) {
                pa[i] = *(const float4*)(A  + (size_t)(m0 + amr + 32 * i) * II + knext + akc);
                pb[i] = *(const float4*)(Bw + (size_t)(knext + bkr + 8 * i) * HH + n0 + bnc);
            }
        }
        #pragma unroll
        for (int kk = 0; kk < 4; ++kk) {
            const int kb = kk * 8;
            uint32_t af[4][4], bf[4][2];
            #pragma unroll
            for (int mt = 0; mt < 4; ++mt) {
                int r = wm * 64 + mt * 16 + (lane >> 2);
                int c = kb + (lane & 3);
                af[mt][0] = __float_as_uint(As[r][c]);
                af[mt][1] = __float_as_uint(As[r + 8][c]);
                af[mt][2] = __float_as_uint(As[r][c + 4]);
                af[mt][3] = __float_as_uint(As[r + 8][c + 4]);
            }
            #pragma unroll
            for (int nt = 0; nt < 4; ++nt) {
                int n = wn * 32 + nt * 8 + (lane >> 2);
                bf[nt][0] = __float_as_uint(Bs[kb + (lane & 3)][n]);
                bf[nt][1] = __float_as_uint(Bs[kb + 4 + (lane & 3)][n]);
            }
            #pragma unroll
            for (int mt = 0; mt < 4; ++mt)
                #pragma unroll
                for (int nt = 0; nt < 4; ++nt)
                    mma_tf32(acc[mt][nt], af[mt], bf[nt]);
        }
        if (knext < II) {
            __syncthreads();
            #pragma unroll
            for (int i = 0; i < 4; ++i) {
                As[amr + 32 * i][akc + 0] = f2tf32(pa[i].x);
                As[amr + 32 * i][akc + 1] = f2tf32(pa[i].y);
                As[amr + 32 * i][akc + 2] = f2tf32(pa[i].z);
                As[amr + 32 * i][akc + 3] = f2tf32(pa[i].w);
                float4 t = pb[i];
                t.x = f2tf32(t.x); t.y = f2tf32(t.y); t.z = f2tf32(t.z); t.w = f2tf32(t.w);
                *(float4*)&Bs[bkr + 8 * i][bnc] = t;
            }
            __syncthreads();
        }
    }

    #pragma unroll
    for (int mt = 0; mt < 4; ++mt) {
        int row = m0 + wm * 64 + mt * 16 + (lane >> 2);
        #pragma unroll
        for (int nt = 0; nt < 4; ++nt) {
            int col = n0 + wn * 32 + nt * 8 + 2 * (lane & 3);
            float b0 = bias[col], b1 = bias[col + 1];
            float2 v0 = {acc[mt][nt][0] + b0, acc[mt][nt][1] + b1};
            float2 v1 = {acc[mt][nt][2] + b0, acc[mt][nt][3] + b1};
            *(float2*)&C[(size_t)row * HH + col]       = v0;
            *(float2*)&C[(size_t)(row + 8) * HH + col] = v1;
        }
    }
}

__global__ __launch_bounds__(256) void gemm_xproj(
    const float* __restrict__ x,
    const float* __restrict__ W0, const float* __restrict__ W1,
    const float* __restrict__ W2, const float* __restrict__ W3,
    const float* __restrict__ b0, const float* __restrict__ b1,
    const float* __restrict__ b2, const float* __restrict__ b3)
{
    const float* Ws[4] = {W0, W1, W2, W3};
    const float* bs[4] = {b0, b1, b2, b3};
    int g = blockIdx.z;
    gemm_tf32_core(x, Ws[g], bs[g], g_XP + (size_t)g * SB * HH);
}

__global__ __launch_bounds__(256) void gemm_outproj(
    const float* __restrict__ Why, const float* __restrict__ bhy,
    float* __restrict__ out)
{
    gemm_tf32_core(g_Hall, Why, bhy, out);
}

// ---------------- Persistent recurrence kernel -------------------------------
// 128 blocks x 256 threads, 1 block/SM (smem-limited) => all co-resident.
// Block bx owns hidden cols [bx*8, bx*8+8) x 4 gates. Weights (128KB) loaded
// to smem ONCE; 512 steps looped internally with a global spin barrier.
// smem: W 32768f | A 3x2048f | XP 2x2048f | pre 64x33f  = ~180KB dynamic.
#define PSTAGES 3
#define PNIT 32

__global__ __launch_bounds__(256) void lstm_persist(
    const float* __restrict__ bi, const float* __restrict__ bf,
    const float* __restrict__ bc, const float* __restrict__ bo)
{
    extern __shared__ __align__(16) float sm[];
    float* Wsm  = sm;                       // 32768
    float* Asm  = sm + 32768;               // 3*2048
    float* XPsm = sm + 32768 + 6144;        // 2*2048
    float* pre  = sm + 32768 + 6144 + 4096; // 64*33

    const int tid  = threadIdx.x;
    const int lane = tid & 31;
    const int w    = tid >> 5;
    const int wm   = w & 3;
    const int wn   = w >> 2;
    const int bx   = blockIdx.x;
    const int c0   = bx * 8;

    const uint32_t sW = (uint32_t)__cvta_generic_to_shared(Wsm);
    const uint32_t sA = (uint32_t)__cvta_generic_to_shared(Asm);
    const uint32_t sX = (uint32_t)__cvta_generic_to_shared(XPsm);

    // ---- load weights once (32768 floats = 8192 x 16B) ----
    {
        const float* Wsrc = g_Wpk + (size_t)bx * 32768;
        #pragma unroll 4
        for (int j = 0; j < 32; ++j) {
            int idx = tid + 256 * j;
            cp_async16(sW + idx * 16, Wsrc + idx * 4);
        }
    }
    // ---- XP prefetch for step 0 ----
    {
        #pragma unroll
        for (int j = 0; j < 2; ++j) {
            int idx  = tid * 2 + j;
            int gate = idx >> 7, row = (idx >> 1) & 63, half = idx & 1;
            const float* src = g_XP + (size_t)gate * SB * HH
                             + (size_t)row * HH + c0 + half * 4;
            cp_async16(sX + (gate * 512 + row * 8 + half * 4) * 4, src);
        }
    }
    cp_commit();

    // per-thread epilogue constants
    const int cc   = tid & 7;
    const int col  = c0 + cc;
    const int row0 = tid >> 3;           // 0..31 (e=1 adds 32)
    const float bI = bi[col], bF = bf[col], bC = bc[col], bO = bo[col];
    float creg[2] = {0.0f, 0.0f};

    for (int t = 0; t < SS; ++t) {
        const float* Asrc = g_HTp[t & 1];
        float*       hout = g_Hall + (size_t)t * BB * HH;
        float*       hTn  = g_HTp[(t + 1) & 1];

        float acc[2][4];
        #pragma unroll
        for (int nt = 0; nt < 2; ++nt)
            #pragma unroll
            for (int r = 0; r < 4; ++r) acc[nt][r] = 0.0f;

        // prologue: A tiles 0,1
        #pragma unroll
        for (int i = 0; i < 2; ++i) {
            #pragma unroll
            for (int j = 0; j < 2; ++j) {
                int idx = tid + 256 * j;
                cp_async16(sA + ((i % PSTAGES) * 2048 + idx * 4) * 4,
                           Asrc + i * 2048 + idx * 4);
            }
            cp_commit();
        }

        for (int it = 0; it < PNIT; ++it) {
            cp_wait<1>();
            __syncthreads();
            if (it + 2 < PNIT) {
                int i = it + 2;
                #pragma unroll
                for (int j = 0; j < 2; ++j) {
                    int idx = tid + 256 * j;
                    cp_async16(sA + ((i % PSTAGES) * 2048 + idx * 4) * 4,
                               Asrc + i * 2048 + idx * 4);
                }
            }
            if (it == 0 && t + 1 < SS) {
                // prefetch XP for step t+1
                int buf = (t + 1) & 1;
                #pragma unroll
                for (int j = 0; j < 2; ++j) {
                    int idx  = tid * 2 + j;
                    int gate = idx >> 7, row = (idx >> 1) & 63, half = idx & 1;
                    const float* src = g_XP + (size_t)gate * SB * HH
                                     + ((size_t)(t + 1) * BB + row) * HH + c0 + half * 4;
                    cp_async16(sX + (buf * 2048 + gate * 512 + row * 8 + half * 4) * 4, src);
                }
            }
            cp_commit();

            const float* Asl = Asm + (it % PSTAGES) * 2048;
            const float* Bsl = Wsm + it * 1024;

            #pragma unroll
            for (int k8 = 0; k8 < 4; ++k8) {
                uint32_t af[4];
                {
                    int base = k8 * 512 + (wm * 16 + (lane >> 2)) * 8 + (lane & 3) * 2;
                    float2 a0 = *(const float2*)(Asl + base);
                    float2 a1 = *(const float2*)(Asl + base + 64);
                    af[0] = __float_as_uint(a0.x);
                    af[1] = __float_as_uint(a1.x);
                    af[2] = __float_as_uint(a0.y);
                    af[3] = __float_as_uint(a1.y);
                }
                #pragma unroll
                for (int nt = 0; nt < 2; ++nt) {
                    int pb = k8 * 256 + (wn * 16 + nt * 8 + (lane >> 2)) * 8 + (lane & 3) * 2;
                    float2 b = *(const float2*)(Bsl + pb);
                    uint32_t bfr[2] = {__float_as_uint(b.x), __float_as_uint(b.y)};
                    mma_tf32(acc[nt], af, bfr);
                }
            }
        }

        // ---- stage pre-activations ----
        #pragma unroll
        for (int nt = 0; nt < 2; ++nt) {
            int r = wm * 16 + (lane >> 2);
            int c = wn * 16 + nt * 8 + 2 * (lane & 3);
            pre[r * 33 + c]           = acc[nt][0];
            pre[r * 33 + c + 1]       = acc[nt][1];
            pre[(r + 8) * 33 + c]     = acc[nt][2];
            pre[(r + 8) * 33 + c + 1] = acc[nt][3];
        }
        cp_wait<0>();
        __syncthreads();

        // ---- fused elementwise epilogue ----
        const float* xp = XPsm + (t & 1) * 2048;
        #pragma unroll
        for (int e = 0; e < 2; ++e) {
            int row = row0 + 32 * e;
            size_t off = (size_t)row * HH + col;

            float pi = pre[row * 33 + cc]      + xp[0 * 512 + row * 8 + cc] + bI;
            float pf = pre[row * 33 + 8 + cc]  + xp[1 * 512 + row * 8 + cc] + bF;
            float pc = pre[row * 33 + 16 + cc] + xp[2 * 512 + row * 8 + cc] + bC;
            float po = pre[row * 33 + 24 + cc] + xp[3 * 512 + row * 8 + cc] + bO;

            float iv = 1.0f / (1.0f + expf(-pi));
            float fv = 1.0f / (1.0f + expf(-pf));
            float ov = 1.0f / (1.0f + expf(-po));
            float gv = tanhf(pc);

            float cv = fv * creg[e] + iv * gv;
            float hv = ov * tanhf(cv);
            creg[e] = cv;

            hout[off] = hv;
            hTn[(((bx * 64 + row)) << 3) + ((col & 3) << 1) + ((col >> 2) & 1)] = f2tf32(hv);
        }

        // ---- grid barrier ----
        if (t + 1 < SS) {
            __threadfence();
            __syncthreads();
            if (tid == 0) {
                atomicAdd(&g_bar, 1u);
                unsigned need = 128u * (unsigned)(t + 1);
                while (*((volatile unsigned*)&g_bar) < need) { __nanosleep(32); }
            }
            __syncthreads();
        }
    }
}

// ---------------- launch -----------------------------------------------------
extern "C" void kernel_launch(void* const* d_in, const int* in_sizes, int n_in,
                              void* d_out, int out_size)
{
    (void)in_sizes; (void)n_in; (void)out_size;

    const float* x    = (const float*)d_in[0];
    const float* Wx[4] = {(const float*)d_in[1], (const float*)d_in[3],
                          (const float*)d_in[5], (const float*)d_in[7]};
    const float* bx[4] = {(const float*)d_in[2], (const float*)d_in[4],
                          (const float*)d_in[6], (const float*)d_in[8]};
    const float* Wh[4] = {(const float*)d_in[9],  (const float*)d_in[11],
                          (const float*)d_in[13], (const float*)d_in[15]};
    const float* bh[4] = {(const float*)d_in[10], (const float*)d_in[12],
                          (const float*)d_in[14], (const float*)d_in[16]};
    const float* Why = (const float*)d_in[17];
    const float* bhy = (const float*)d_in[18];
    float* out = (float*)d_out;

    static int smem_set = 0;
    const int psmem = (32768 + 3 * 2048 + 2 * 2048 + 64 * 33) * 4;
    if (!smem_set) {
        cudaFuncSetAttribute(lstm_persist,
                             cudaFuncAttributeMaxDynamicSharedMemorySize, psmem);
        smem_set = 1;
    }

    init_state_kernel<<<(BB * HH + 255) / 256, 256>>>();
    repack_w<<<(128 * 128 * 32 * 8) / 256, 256>>>(Wh[0], Wh[1], Wh[2], Wh[3]);

    {
        dim3 grid(HH / BN, SB / BM, 4);
        gemm_xproj<<<grid, 256>>>(x, Wx[0], Wx[1], Wx[2], Wx[3],
                                     bx[0], bx[1], bx[2], bx[3]);
    }

    lstm_persist<<<128, 256, psmem>>>(bh[0], bh[1], bh[2], bh[3]);

    {
        dim3 grid(HH / BN, SB / BM);
        gemm_outproj<<<grid, 256>>>(Why, bhy, out);
    }
}

// round 6
// speedup vs baseline: 4.5205x; 1.0958x over previous
#include <cuda_runtime.h>
#include <math.h>
#include <stdint.h>

#define SS 512
#define BB 64
#define II 1024
#define HH 1024
#define SB (SS*BB)

// ---------------- scratch (static device globals; no allocation) -------------
__device__ float g_XP[4ULL * SB * HH];          // input projections [4][S*B][H]
__device__ float g_Hall[(size_t)SB * HH];       // h_t row-major [S][B][H]
__device__ float g_HTp[2][HH * BB];             // h transposed+pair-packed, ping-pong
__device__ float g_Wpk[128ULL * 128 * 32 * 8];  // packed recurrent weights
__device__ unsigned g_bar;                       // grid barrier (monotonic)

// ---------------- helpers ----------------------------------------------------
__device__ __forceinline__ float f2tf32(float f) {
    uint32_t r;
    asm("cvt.rna.tf32.f32 %0, %1;" : "=r"(r) : "f"(f));
    return __uint_as_float(r);
}

__device__ __forceinline__ void mma_tf32(float c[4], const uint32_t a[4], const uint32_t b[2]) {
    asm volatile(
        "mma.sync.aligned.m16n8k8.row.col.f32.tf32.tf32.f32 "
        "{%0,%1,%2,%3}, {%4,%5,%6,%7}, {%8,%9}, {%0,%1,%2,%3};"
        : "+f"(c[0]), "+f"(c[1]), "+f"(c[2]), "+f"(c[3])
        : "r"(a[0]), "r"(a[1]), "r"(a[2]), "r"(a[3]), "r"(b[0]), "r"(b[1]));
}

__device__ __forceinline__ void cp_async16(uint32_t dst_smem, const void* src) {
    asm volatile("cp.async.cg.shared.global [%0], [%1], 16;" :: "r"(dst_smem), "l"(src));
}
__device__ __forceinline__ void cp_commit() { asm volatile("cp.async.commit_group;"); }
template<int N> __device__ __forceinline__ void cp_wait() {
    asm volatile("cp.async.wait_group %0;" :: "n"(N));
}

// ---------------- init -------------------------------------------------------
__global__ void init_state_kernel() {
    int idx = blockIdx.x * blockDim.x + threadIdx.x;
    if (idx < BB * HH) g_HTp[0][idx] = 0.0f;
    if (idx == 0) g_bar = 0u;
}

// ---------------- weight repack ----------------------------------------------
__global__ __launch_bounds__(256) void repack_w(
    const float* __restrict__ Wi, const float* __restrict__ Wf,
    const float* __restrict__ Wc, const float* __restrict__ Wo)
{
    const float* W[4] = {Wi, Wf, Wc, Wo};
    int n = blockIdx.x * blockDim.x + threadIdx.x;
    int hi   = n & 1;
    int p    = (n >> 1) & 3;
    int pcol = (n >> 3) & 31;
    int k8   = (n >> 8) & 127;
    int bx   = n >> 15;
    int gate = pcol >> 3;
    int col  = bx * 8 + (pcol & 7);
    int k    = k8 * 8 + p + hi * 4;
    g_Wpk[n] = f2tf32(W[gate][(size_t)k * HH + col]);
}

// ---------------- big tf32 GEMM (unchanged) ----------------------------------
#define BM 128
#define BN 128
#define BKK 32

__device__ __forceinline__ void gemm_tf32_core(
    const float* __restrict__ A, const float* __restrict__ Bw,
    const float* __restrict__ bias, float* __restrict__ C)
{
    __shared__ __align__(16) float As[BM][BKK + 4];
    __shared__ __align__(16) float Bs[BKK][BN + 4];

    const int tid  = threadIdx.x;
    const int lane = tid & 31;
    const int w    = tid >> 5;
    const int wm   = w & 1;
    const int wn   = w >> 1;

    const int m0 = blockIdx.y * BM;
    const int n0 = blockIdx.x * BN;

    const int amr = tid >> 3;
    const int akc = (tid & 7) * 4;
    const int bkr = tid >> 5;
    const int bnc = (tid & 31) * 4;

    float acc[4][4][4];
    #pragma unroll
    for (int i = 0; i < 4; ++i)
        #pragma unroll
        for (int j = 0; j < 4; ++j)
            #pragma unroll
            for (int r = 0; r < 4; ++r) acc[i][j][r] = 0.0f;

    float4 pa[4], pb[4];
    #pragma unroll
    for (int i = 0; i < 4; ++i) {
        pa[i] = *(const float4*)(A  + (size_t)(m0 + amr + 32 * i) * II + akc);
        pb[i] = *(const float4*)(Bw + (size_t)(bkr + 8 * i) * HH + n0 + bnc);
    }
    #pragma unroll
    for (int i = 0; i < 4; ++i) {
        As[amr + 32 * i][akc + 0] = f2tf32(pa[i].x);
        As[amr + 32 * i][akc + 1] = f2tf32(pa[i].y);
        As[amr + 32 * i][akc + 2] = f2tf32(pa[i].z);
        As[amr + 32 * i][akc + 3] = f2tf32(pa[i].w);
        float4 t = pb[i];
        t.x = f2tf32(t.x); t.y = f2tf32(t.y); t.z = f2tf32(t.z); t.w = f2tf32(t.w);
        *(float4*)&Bs[bkr + 8 * i][bnc] = t;
    }
    __syncthreads();

    const int NT = II / BKK;
    for (int it = 0; it < NT; ++it) {
        const int knext = (it + 1) * BKK;
        if (knext < II) {
            #pragma unroll
            for (int i = 0; i < 4; ++i) {
                pa[i] = *(const float4*)(A  + (size_t)(m0 + amr + 32 * i) * II + knext + akc);
                pb[i] = *(const float4*)(Bw + (size_t)(knext + bkr + 8 * i) * HH + n0 + bnc);
            }
        }
        #pragma unroll
        for (int kk = 0; kk < 4; ++kk) {
            const int kb = kk * 8;
            uint32_t af[4][4], bf[4][2];
            #pragma unroll
            for (int mt = 0; mt < 4; ++mt) {
                int r = wm * 64 + mt * 16 + (lane >> 2);
                int c = kb + (lane & 3);
                af[mt][0] = __float_as_uint(As[r][c]);
                af[mt][1] = __float_as_uint(As[r + 8][c]);
                af[mt][2] = __float_as_uint(As[r][c + 4]);
                af[mt][3] = __float_as_uint(As[r + 8][c + 4]);
            }
            #pragma unroll
            for (int nt = 0; nt < 4; ++nt) {
                int n = wn * 32 + nt * 8 + (lane >> 2);
                bf[nt][0] = __float_as_uint(Bs[kb + (lane & 3)][n]);
                bf[nt][1] = __float_as_uint(Bs[kb + 4 + (lane & 3)][n]);
            }
            #pragma unroll
            for (int mt = 0; mt < 4; ++mt)
                #pragma unroll
                for (int nt = 0; nt < 4; ++nt)
                    mma_tf32(acc[mt][nt], af[mt], bf[nt]);
        }
        if (knext < II) {
            __syncthreads();
            #pragma unroll
            for (int i = 0; i < 4; ++i) {
                As[amr + 32 * i][akc + 0] = f2tf32(pa[i].x);
                As[amr + 32 * i][akc + 1] = f2tf32(pa[i].y);
                As[amr + 32 * i][akc + 2] = f2tf32(pa[i].z);
                As[amr + 32 * i][akc + 3] = f2tf32(pa[i].w);
                float4 t = pb[i];
                t.x = f2tf32(t.x); t.y = f2tf32(t.y); t.z = f2tf32(t.z); t.w = f2tf32(t.w);
                *(float4*)&Bs[bkr + 8 * i][bnc] = t;
            }
            __syncthreads();
        }
    }

    #pragma unroll
    for (int mt = 0; mt < 4; ++mt) {
        int row = m0 + wm * 64 + mt * 16 + (lane >> 2);
        #pragma unroll
        for (int nt = 0; nt < 4; ++nt) {
            int col = n0 + wn * 32 + nt * 8 + 2 * (lane & 3);
            float b0 = bias[col], b1 = bias[col + 1];
            float2 v0 = {acc[mt][nt][0] + b0, acc[mt][nt][1] + b1};
            float2 v1 = {acc[mt][nt][2] + b0, acc[mt][nt][3] + b1};
            *(float2*)&C[(size_t)row * HH + col]       = v0;
            *(float2*)&C[(size_t)(row + 8) * HH + col] = v1;
        }
    }
}

__global__ __launch_bounds__(256) void gemm_xproj(
    const float* __restrict__ x,
    const float* __restrict__ W0, const float* __restrict__ W1,
    const float* __restrict__ W2, const float* __restrict__ W3,
    const float* __restrict__ b0, const float* __restrict__ b1,
    const float* __restrict__ b2, const float* __restrict__ b3)
{
    const float* Ws[4] = {W0, W1, W2, W3};
    const float* bs[4] = {b0, b1, b2, b3};
    int g = blockIdx.z;
    gemm_tf32_core(x, Ws[g], bs[g], g_XP + (size_t)g * SB * HH);
}

__global__ __launch_bounds__(256) void gemm_outproj(
    const float* __restrict__ Why, const float* __restrict__ bhy,
    float* __restrict__ out)
{
    gemm_tf32_core(g_Hall, Why, bhy, out);
}

// ---------------- Persistent recurrence kernel -------------------------------
// 128 blocks x 512 threads, 1 block/SM => all co-resident.
// Block bx owns hidden cols [bx*8, bx*8+8) x 4 gates (32 pre-cols).
// 16 warps = 4 m-tiles(16 rows) x 4 n-tiles(8 pcols). Weights in smem once.
// 5-stage cp.async pipeline on A (h broadcast): slack = 4 iterations.
// smem: W 32768f | A 5x2048f | XP 2x2048f | pre 64x33f  ~= 197KB
#define PSTAGES 5
#define PNIT 32

__global__ __launch_bounds__(512) void lstm_persist(
    const float* __restrict__ bi, const float* __restrict__ bf,
    const float* __restrict__ bc, const float* __restrict__ bo)
{
    extern __shared__ __align__(16) float sm[];
    float* Wsm  = sm;                                  // 32768
    float* Asm  = sm + 32768;                          // 5*2048
    float* XPsm = sm + 32768 + PSTAGES * 2048;         // 2*2048
    float* pre  = XPsm + 4096;                         // 64*33

    const int tid  = threadIdx.x;
    const int lane = tid & 31;
    const int w    = tid >> 5;
    const int wm   = w & 3;        // m-tile (16 rows)
    const int wn   = w >> 2;       // n-tile (8 pcols)
    const int bx   = blockIdx.x;
    const int c0   = bx * 8;

    const uint32_t sW = (uint32_t)__cvta_generic_to_shared(Wsm);
    const uint32_t sA = (uint32_t)__cvta_generic_to_shared(Asm);
    const uint32_t sX = (uint32_t)__cvta_generic_to_shared(XPsm);

    // ---- load weights once (32768 floats = 8192 x 16B, 512 thr x 16) ----
    {
        const float* Wsrc = g_Wpk + (size_t)bx * 32768;
        #pragma unroll 4
        for (int j = 0; j < 16; ++j) {
            int idx = tid + 512 * j;
            cp_async16(sW + idx * 16, Wsrc + idx * 4);
        }
    }
    // ---- XP prefetch for step 0 (2048 floats, 1 x 16B per thread) ----
    {
        int gate = tid >> 7, row = (tid >> 1) & 63, half = tid & 1;
        const float* src = g_XP + (size_t)gate * SB * HH
                         + (size_t)row * HH + c0 + half * 4;
        cp_async16(sX + (gate * 512 + row * 8 + half * 4) * 4, src);
    }
    cp_commit();

    // per-thread epilogue constants: 1 element per thread
    const int cc  = tid & 7;
    const int col = c0 + cc;
    const int row = tid >> 3;            // 0..63
    const float bI = bi[col], bF = bf[col], bC = bc[col], bO = bo[col];
    float creg = 0.0f;

    for (int t = 0; t < SS; ++t) {
        const float* Asrc = g_HTp[t & 1];
        float*       hout = g_Hall + (size_t)t * BB * HH;
        float*       hTn  = g_HTp[(t + 1) & 1];

        float acc[4];
        #pragma unroll
        for (int r = 0; r < 4; ++r) acc[r] = 0.0f;

        // prologue: A tiles 0..3 (one 16B cp per thread per tile)
        #pragma unroll
        for (int i = 0; i < PSTAGES - 1; ++i) {
            cp_async16(sA + ((i % PSTAGES) * 2048 + tid * 4) * 4,
                       Asrc + i * 2048 + tid * 4);
            cp_commit();
        }

        for (int it = 0; it < PNIT; ++it) {
            cp_wait<PSTAGES - 2>();
            __syncthreads();
            if (it + PSTAGES - 1 < PNIT) {
                int i = it + PSTAGES - 1;
                cp_async16(sA + ((i % PSTAGES) * 2048 + tid * 4) * 4,
                           Asrc + i * 2048 + tid * 4);
            }
            if (it == 0 && t + 1 < SS) {
                // prefetch XP for step t+1
                int buf  = (t + 1) & 1;
                int gate = tid >> 7, r2 = (tid >> 1) & 63, half = tid & 1;
                const float* src = g_XP + (size_t)gate * SB * HH
                                 + ((size_t)(t + 1) * BB + r2) * HH + c0 + half * 4;
                cp_async16(sX + (buf * 2048 + gate * 512 + r2 * 8 + half * 4) * 4, src);
            }
            cp_commit();

            const float* Asl = Asm + (it % PSTAGES) * 2048;
            const float* Bsl = Wsm + it * 1024;

            #pragma unroll
            for (int k8 = 0; k8 < 4; ++k8) {
                uint32_t af[4];
                {
                    int base = k8 * 512 + (wm * 16 + (lane >> 2)) * 8 + (lane & 3) * 2;
                    float2 a0 = *(const float2*)(Asl + base);
                    float2 a1 = *(const float2*)(Asl + base + 64);
                    af[0] = __float_as_uint(a0.x);
                    af[1] = __float_as_uint(a1.x);
                    af[2] = __float_as_uint(a0.y);
                    af[3] = __float_as_uint(a1.y);
                }
                int pb = k8 * 256 + (wn * 8 + (lane >> 2)) * 8 + (lane & 3) * 2;
                float2 b = *(const float2*)(Bsl + pb);
                uint32_t bfr[2] = {__float_as_uint(b.x), __float_as_uint(b.y)};
                mma_tf32(acc, af, bfr);
            }
        }

        // ---- stage pre-activations ----
        {
            int r = wm * 16 + (lane >> 2);
            int c = wn * 8 + 2 * (lane & 3);
            pre[r * 33 + c]           = acc[0];
            pre[r * 33 + c + 1]       = acc[1];
            pre[(r + 8) * 33 + c]     = acc[2];
            pre[(r + 8) * 33 + c + 1] = acc[3];
        }
        cp_wait<0>();
        __syncthreads();

        // ---- fused elementwise epilogue: 1 element/thread ----
        const float* xp = XPsm + (t & 1) * 2048;
        {
            size_t off = (size_t)row * HH + col;

            float pi = pre[row * 33 + cc]      + xp[0 * 512 + row * 8 + cc] + bI;
            float pf = pre[row * 33 + 8 + cc]  + xp[1 * 512 + row * 8 + cc] + bF;
            float pc = pre[row * 33 + 16 + cc] + xp[2 * 512 + row * 8 + cc] + bC;
            float po = pre[row * 33 + 24 + cc] + xp[3 * 512 + row * 8 + cc] + bO;

            float iv = 1.0f / (1.0f + expf(-pi));
            float fv = 1.0f / (1.0f + expf(-pf));
            float ov = 1.0f / (1.0f + expf(-po));
            float gv = tanhf(pc);

            float cv = fv * creg + iv * gv;
            float hv = ov * tanhf(cv);
            creg = cv;

            hout[off] = hv;
            hTn[((bx * 64 + row) << 3) + ((col & 3) << 1) + ((col >> 2) & 1)] = f2tf32(hv);
        }

        // ---- grid barrier ----
        if (t + 1 < SS) {
            __threadfence();
            __syncthreads();
            if (tid == 0) {
                atomicAdd(&g_bar, 1u);
                unsigned need = 128u * (unsigned)(t + 1);
                while (*((volatile unsigned*)&g_bar) < need) { __nanosleep(16); }
            }
            __syncthreads();
        }
    }
}

// ---------------- launch -----------------------------------------------------
extern "C" void kernel_launch(void* const* d_in, const int* in_sizes, int n_in,
                              void* d_out, int out_size)
{
    (void)in_sizes; (void)n_in; (void)out_size;

    const float* x    = (const float*)d_in[0];
    const float* Wx[4] = {(const float*)d_in[1], (const float*)d_in[3],
                          (const float*)d_in[5], (const float*)d_in[7]};
    const float* bx[4] = {(const float*)d_in[2], (const float*)d_in[4],
                          (const float*)d_in[6], (const float*)d_in[8]};
    const float* Wh[4] = {(const float*)d_in[9],  (const float*)d_in[11],
                          (const float*)d_in[13], (const float*)d_in[15]};
    const float* bh[4] = {(const float*)d_in[10], (const float*)d_in[12],
                          (const float*)d_in[14], (const float*)d_in[16]};
    const float* Why = (const float*)d_in[17];
    const float* bhy = (const float*)d_in[18];
    float* out = (float*)d_out;

    static int smem_set = 0;
    const int psmem = (32768 + PSTAGES * 2048 + 2 * 2048 + 64 * 33) * 4;
    if (!smem_set) {
        cudaFuncSetAttribute(lstm_persist,
                             cudaFuncAttributeMaxDynamicSharedMemorySize, psmem);
        smem_set = 1;
    }

    init_state_kernel<<<(BB * HH + 255) / 256, 256>>>();
    repack_w<<<(128 * 128 * 32 * 8) / 256, 256>>>(Wh[0], Wh[1], Wh[2], Wh[3]);

    {
        dim3 grid(HH / BN, SB / BM, 4);
        gemm_xproj<<<grid, 256>>>(x, Wx[0], Wx[1], Wx[2], Wx[3],
                                     bx[0], bx[1], bx[2], bx[3]);
    }

    lstm_persist<<<128, 512, psmem>>>(bh[0], bh[1], bh[2], bh[3]);

    {
        dim3 grid(HH / BN, SB / BM);
        gemm_outproj<<<grid, 256>>>(Why, bhy, out);
    }
}